// round 10
// baseline (speedup 1.0000x reference)
#include <cuda_runtime.h>

// out[e] = sigmoid( dot( x[src[e], 0:128], x[dst[e], 128:256] ) )
// x: [100000, 256] fp32. edge_label_index: [2, N_EDGES] int32 on device.
//
// 8 edges per warp. Gathers use LDG.32 (lane l loads cols l, l+32, l+64,
// l+96): each load covers exactly one 128B line = 1 L1 wavefront at the
// 1.0 cyc cross-LDG rate, avoiding the 2.07 cyc within-LDG replay cost of
// LDG.128 (which spans 4 lines per instruction).
// Merging butterfly: 16 SHFLs reduce all 8 edge dots at once; lane l ends
// holding edge (l & 7) -> lanes 0-7 do parallel sigmoids + one 32B store.

#define HIDDEN 256
#define HALF   128
#define EPW    8     // edges per warp

__device__ __forceinline__ float sigmoidf(float v)
{
    return 1.0f / (1.0f + __expf(-v));
}

__global__ __launch_bounds__(256)
void edge_dot_sigmoid_kernel(const float* __restrict__ x,
                             const int* __restrict__ eidx,
                             float* __restrict__ out,
                             int n_edges)
{
    int warp = (blockIdx.x * blockDim.x + threadIdx.x) >> 5;
    int lane = threadIdx.x & 31;
    int base = warp * EPW;
    if (base >= n_edges) return;

    if (base + EPW <= n_edges) {
        // Warp-uniform vector index loads (16B requests).
        int4 s0 = __ldg(reinterpret_cast<const int4*>(eidx + base));
        int4 s1 = __ldg(reinterpret_cast<const int4*>(eidx + base + 4));
        int4 d0 = __ldg(reinterpret_cast<const int4*>(eidx + n_edges + base));
        int4 d1 = __ldg(reinterpret_cast<const int4*>(eidx + n_edges + base + 4));
        int s[EPW] = {s0.x, s0.y, s0.z, s0.w, s1.x, s1.y, s1.z, s1.w};
        int d[EPW] = {d0.x, d0.y, d0.z, d0.w, d1.x, d1.y, d1.z, d1.w};

        // Row base pointers (lane-relative).
        const float* sp[EPW];
        const float* dp[EPW];
        #pragma unroll
        for (int k = 0; k < EPW; k++) {
            sp[k] = x + (long long)s[k] * HIDDEN + lane;         // cols [0,128)
            dp[k] = x + (long long)d[k] * HIDDEN + HALF + lane;  // cols [128,256)
        }

        // Issue all 64 single-line gathers before any math.
        float a[EPW][4], b[EPW][4];
        #pragma unroll
        for (int k = 0; k < EPW; k++) {
            #pragma unroll
            for (int j = 0; j < 4; j++)
                a[k][j] = __ldg(sp[k] + 32 * j);
        }
        #pragma unroll
        for (int k = 0; k < EPW; k++) {
            #pragma unroll
            for (int j = 0; j < 4; j++)
                b[k][j] = __ldg(dp[k] + 32 * j);
        }

        float v[EPW];
        #pragma unroll
        for (int k = 0; k < EPW; k++)
            v[k] = a[k][0] * b[k][0] + a[k][1] * b[k][1]
                 + a[k][2] * b[k][2] + a[k][3] * b[k][3];

        // Merging butterfly: 8 -> 4 -> 2 -> 1 arrays, then finish the tree.
        float m0[4];
        #pragma unroll
        for (int k = 0; k < 4; k++) {
            float e0 = v[2*k]   + __shfl_xor_sync(0xffffffffu, v[2*k],   1);
            float e1 = v[2*k+1] + __shfl_xor_sync(0xffffffffu, v[2*k+1], 1);
            m0[k] = (lane & 1) ? e1 : e0;
        }
        float m1[2];
        #pragma unroll
        for (int k = 0; k < 2; k++) {
            float e0 = m0[2*k]   + __shfl_xor_sync(0xffffffffu, m0[2*k],   2);
            float e1 = m0[2*k+1] + __shfl_xor_sync(0xffffffffu, m0[2*k+1], 2);
            m1[k] = (lane & 2) ? e1 : e0;
        }
        float e0 = m1[0] + __shfl_xor_sync(0xffffffffu, m1[0], 4);
        float e1 = m1[1] + __shfl_xor_sync(0xffffffffu, m1[1], 4);
        float m2 = (lane & 4) ? e1 : e0;
        m2 += __shfl_xor_sync(0xffffffffu, m2, 8);
        m2 += __shfl_xor_sync(0xffffffffu, m2, 16);
        // lane l now holds the full dot for edge (l & 7).

        if (lane < EPW)
            out[base + lane] = sigmoidf(m2);
    } else {
        // Tail: up to EPW-1 edges, scalar path.
        for (int e = base; e < n_edges; e++) {
            int s = __ldg(&eidx[e]);
            int d = __ldg(&eidx[n_edges + e]);
            const float* sp = x + (long long)s * HIDDEN + lane;
            const float* dp = x + (long long)d * HIDDEN + HALF + lane;
            float dot = 0.0f;
            #pragma unroll
            for (int j = 0; j < 4; j++)
                dot += __ldg(sp + 32 * j) * __ldg(dp + 32 * j);
            #pragma unroll
            for (int off = 16; off > 0; off >>= 1)
                dot += __shfl_xor_sync(0xffffffffu, dot, off);
            if (lane == 0)
                out[e] = sigmoidf(dot);
        }
    }
}

extern "C" void kernel_launch(void* const* d_in, const int* in_sizes, int n_in,
                              void* d_out, int out_size)
{
    const float* x    = (const float*)d_in[0];
    const int*   eidx = (const int*)d_in[1];
    float*       out  = (float*)d_out;

    int n_edges = in_sizes[1] / 2;   // edge_label_index has 2*N_EDGES elements

    const int threads = 256;                       // 8 warps/block
    int warps_per_block = threads / 32;
    int edges_per_block = warps_per_block * EPW;
    int blocks = (n_edges + edges_per_block - 1) / edges_per_block;

    edge_dot_sigmoid_kernel<<<blocks, threads>>>(x, eidx, out, n_edges);
}

// round 11
// speedup vs baseline: 1.2428x; 1.2428x over previous
#include <cuda_runtime.h>
#include <cuda_fp16.h>

// out[e] = sigmoid( dot( x[src[e], 0:128], x[dst[e], 128:256] ) )
// x: [100000, 256] fp32. edge_label_index: [2, N_EDGES] int32 on device.
//
// Two kernels per launch:
//  1) convert x (102 MB fp32) -> static __device__ fp16 table (51.2 MB,
//     fits in the 126 MB L2) — fp32 accumulation downstream keeps error
//     ~1e-4, under the 1e-3 gate.
//  2) gather: 8 edges/warp, per-lane LDG.64 (4 halves) per half-row
//     -> 256 B/edge instead of 512 B; merging-butterfly reduction.

#define N_NODES 100000
#define HIDDEN  256
#define HALF    128
#define EPW     8     // edges per warp

__device__ static __half g_xh[(size_t)N_NODES * HIDDEN];   // 51.2 MB scratch

__device__ __forceinline__ float sigmoidf(float v)
{
    return 1.0f / (1.0f + __expf(-v));
}

// ---------------- kernel 1: fp32 -> fp16 table ----------------
__global__ __launch_bounds__(256)
void convert_kernel(const float* __restrict__ x, int n4)
{
    int i = blockIdx.x * blockDim.x + threadIdx.x;
    if (i >= n4) return;
    float4 v = __ldg(reinterpret_cast<const float4*>(x) + i);
    __half2 h0 = __floats2half2_rn(v.x, v.y);
    __half2 h1 = __floats2half2_rn(v.z, v.w);
    uint2 u;
    u.x = *reinterpret_cast<unsigned*>(&h0);
    u.y = *reinterpret_cast<unsigned*>(&h1);
    reinterpret_cast<uint2*>(g_xh)[i] = u;
}

// unpack uint2 (4 halves) and accumulate into fp32 dot
__device__ __forceinline__ float dot4h(uint2 ua, uint2 ub)
{
    __half2 a0 = *reinterpret_cast<__half2*>(&ua.x);
    __half2 a1 = *reinterpret_cast<__half2*>(&ua.y);
    __half2 b0 = *reinterpret_cast<__half2*>(&ub.x);
    __half2 b1 = *reinterpret_cast<__half2*>(&ub.y);
    float2 fa0 = __half22float2(a0), fa1 = __half22float2(a1);
    float2 fb0 = __half22float2(b0), fb1 = __half22float2(b1);
    return fa0.x * fb0.x + fa0.y * fb0.y + fa1.x * fb1.x + fa1.y * fb1.y;
}

// ---------------- kernel 2: edge gather + dot + sigmoid ----------------
__global__ __launch_bounds__(256)
void edge_dot_sigmoid_kernel(const int* __restrict__ eidx,
                             float* __restrict__ out,
                             int n_edges)
{
    int warp = (blockIdx.x * blockDim.x + threadIdx.x) >> 5;
    int lane = threadIdx.x & 31;
    int base = warp * EPW;
    if (base >= n_edges) return;

    if (base + EPW <= n_edges) {
        // Warp-uniform vector index loads (16B requests).
        int4 s0 = __ldg(reinterpret_cast<const int4*>(eidx + base));
        int4 s1 = __ldg(reinterpret_cast<const int4*>(eidx + base + 4));
        int4 d0 = __ldg(reinterpret_cast<const int4*>(eidx + n_edges + base));
        int4 d1 = __ldg(reinterpret_cast<const int4*>(eidx + n_edges + base + 4));
        int s[EPW] = {s0.x, s0.y, s0.z, s0.w, s1.x, s1.y, s1.z, s1.w};
        int d[EPW] = {d0.x, d0.y, d0.z, d0.w, d1.x, d1.y, d1.z, d1.w};

        // Issue all 16 LDG.64 gathers before any math (each half-row = 256B
        // = 2 lines per warp).
        uint2 a[EPW], b[EPW];
        #pragma unroll
        for (int k = 0; k < EPW; k++)
            a[k] = __ldg(reinterpret_cast<const uint2*>(
                       g_xh + (long long)s[k] * HIDDEN) + lane);
        #pragma unroll
        for (int k = 0; k < EPW; k++)
            b[k] = __ldg(reinterpret_cast<const uint2*>(
                       g_xh + (long long)d[k] * HIDDEN + HALF) + lane);

        float v[EPW];
        #pragma unroll
        for (int k = 0; k < EPW; k++)
            v[k] = dot4h(a[k], b[k]);

        // Merging butterfly: 8 -> 4 -> 2 -> 1 arrays, then finish the tree.
        float m0[4];
        #pragma unroll
        for (int k = 0; k < 4; k++) {
            float e0 = v[2*k]   + __shfl_xor_sync(0xffffffffu, v[2*k],   1);
            float e1 = v[2*k+1] + __shfl_xor_sync(0xffffffffu, v[2*k+1], 1);
            m0[k] = (lane & 1) ? e1 : e0;
        }
        float m1[2];
        #pragma unroll
        for (int k = 0; k < 2; k++) {
            float e0 = m0[2*k]   + __shfl_xor_sync(0xffffffffu, m0[2*k],   2);
            float e1 = m0[2*k+1] + __shfl_xor_sync(0xffffffffu, m0[2*k+1], 2);
            m1[k] = (lane & 2) ? e1 : e0;
        }
        float e0 = m1[0] + __shfl_xor_sync(0xffffffffu, m1[0], 4);
        float e1 = m1[1] + __shfl_xor_sync(0xffffffffu, m1[1], 4);
        float m2 = (lane & 4) ? e1 : e0;
        m2 += __shfl_xor_sync(0xffffffffu, m2, 8);
        m2 += __shfl_xor_sync(0xffffffffu, m2, 16);
        // lane l now holds the full dot for edge (l & 7).

        if (lane < EPW)
            out[base + lane] = sigmoidf(m2);
    } else {
        // Tail: up to EPW-1 edges, scalar path.
        for (int e = base; e < n_edges; e++) {
            int s = __ldg(&eidx[e]);
            int d = __ldg(&eidx[n_edges + e]);
            uint2 a = __ldg(reinterpret_cast<const uint2*>(
                          g_xh + (long long)s * HIDDEN) + lane);
            uint2 b = __ldg(reinterpret_cast<const uint2*>(
                          g_xh + (long long)d * HIDDEN + HALF) + lane);
            float dot = dot4h(a, b);
            #pragma unroll
            for (int off = 16; off > 0; off >>= 1)
                dot += __shfl_xor_sync(0xffffffffu, dot, off);
            if (lane == 0)
                out[e] = sigmoidf(dot);
        }
    }
}

extern "C" void kernel_launch(void* const* d_in, const int* in_sizes, int n_in,
                              void* d_out, int out_size)
{
    const float* x    = (const float*)d_in[0];
    const int*   eidx = (const int*)d_in[1];
    float*       out  = (float*)d_out;

    int n_x     = in_sizes[0];       // 25.6M floats
    int n_edges = in_sizes[1] / 2;   // edge_label_index has 2*N_EDGES elements

    // Kernel 1: convert table to fp16.
    int n4 = n_x / 4;
    convert_kernel<<<(n4 + 255) / 256, 256>>>(x, n4);

    // Kernel 2: gather + dot + sigmoid.
    const int threads = 256;                       // 8 warps/block
    int warps_per_block = threads / 32;
    int edges_per_block = warps_per_block * EPW;
    int blocks = (n_edges + edges_per_block - 1) / edges_per_block;
    edge_dot_sigmoid_kernel<<<blocks, threads>>>(eidx, out, n_edges);
}

// round 12
// speedup vs baseline: 1.3005x; 1.0465x over previous
#include <cuda_runtime.h>
#include <cuda_fp16.h>

// out[e] = sigmoid( dot( x[src[e], 0:128], x[dst[e], 128:256] ) )
// x: [100000, 256] fp32. edge_label_index: [2, N_EDGES] int32 on device.
//
// Two kernels per launch:
//  1) convert x (102 MB fp32) -> static __device__ fp16 table (51.2 MB,
//     L2-resident). fp32 accumulation downstream keeps rel_err ~3.7e-4.
//  2) gather: 8 edges/warp, TWO edges per LDG.128 (a 128-half half-row is
//     256 B = 16 lanes x 16 B): 8 gather instructions instead of 16,
//     relieving the 1.82 cyc/LDG LSU accept floor. 16-lane merging
//     butterfly (8 SHFLs for 8 edges).

#define N_NODES 100000
#define HIDDEN  256
#define HALF    128
#define EPW     8     // edges per warp

__device__ static __half g_xh[(size_t)N_NODES * HIDDEN];   // 51.2 MB scratch

__device__ __forceinline__ float sigmoidf(float v)
{
    return 1.0f / (1.0f + __expf(-v));
}

// ---------------- kernel 1: fp32 -> fp16 table ----------------
__global__ __launch_bounds__(256)
void convert_kernel(const float* __restrict__ x, int n8)
{
    int i = blockIdx.x * blockDim.x + threadIdx.x;
    if (i >= n8) return;
    float4 v0 = __ldg(reinterpret_cast<const float4*>(x) + 2 * i);
    float4 v1 = __ldg(reinterpret_cast<const float4*>(x) + 2 * i + 1);
    __half2 h0 = __floats2half2_rn(v0.x, v0.y);
    __half2 h1 = __floats2half2_rn(v0.z, v0.w);
    __half2 h2 = __floats2half2_rn(v1.x, v1.y);
    __half2 h3 = __floats2half2_rn(v1.z, v1.w);
    uint4 u;
    u.x = *reinterpret_cast<unsigned*>(&h0);
    u.y = *reinterpret_cast<unsigned*>(&h1);
    u.z = *reinterpret_cast<unsigned*>(&h2);
    u.w = *reinterpret_cast<unsigned*>(&h3);
    reinterpret_cast<uint4*>(g_xh)[i] = u;
}

// dot of 8 halves vs 8 halves, fp32 accumulation
__device__ __forceinline__ float dot8h(uint4 ua, uint4 ub)
{
    const __half2* ah = reinterpret_cast<const __half2*>(&ua);
    const __half2* bh = reinterpret_cast<const __half2*>(&ub);
    float acc = 0.0f;
    #pragma unroll
    for (int i = 0; i < 4; i++) {
        float2 fa = __half22float2(ah[i]);
        float2 fb = __half22float2(bh[i]);
        acc = fmaf(fa.x, fb.x, acc);
        acc = fmaf(fa.y, fb.y, acc);
    }
    return acc;
}

// ---------------- kernel 2: edge gather + dot + sigmoid ----------------
__global__ __launch_bounds__(256)
void edge_dot_sigmoid_kernel(const int* __restrict__ eidx,
                             float* __restrict__ out,
                             int n_edges)
{
    int warp = (blockIdx.x * blockDim.x + threadIdx.x) >> 5;
    int lane = threadIdx.x & 31;
    int base = warp * EPW;
    if (base >= n_edges) return;

    if (base + EPW <= n_edges) {
        // Warp-uniform vector index loads (16B requests).
        int4 s0 = __ldg(reinterpret_cast<const int4*>(eidx + base));
        int4 s1 = __ldg(reinterpret_cast<const int4*>(eidx + base + 4));
        int4 d0 = __ldg(reinterpret_cast<const int4*>(eidx + n_edges + base));
        int4 d1 = __ldg(reinterpret_cast<const int4*>(eidx + n_edges + base + 4));
        int s[EPW] = {s0.x, s0.y, s0.z, s0.w, s1.x, s1.y, s1.z, s1.w};
        int d[EPW] = {d0.x, d0.y, d0.z, d0.w, d1.x, d1.y, d1.z, d1.w};

        int hi   = lane >> 4;        // 0: low half-warp, 1: high half-warp
        int sub  = lane & 15;        // position within the 16-lane row load

        // Per chunk k: lanes 0-15 gather edge 2k, lanes 16-31 edge 2k+1.
        // Each half-row (128 halves = 256 B) = 16 lanes x uint4.
        uint4 a[4], b[4];
        #pragma unroll
        for (int k = 0; k < 4; k++) {
            int se = hi ? s[2*k+1] : s[2*k];
            a[k] = __ldg(reinterpret_cast<const uint4*>(
                       g_xh + (long long)se * HIDDEN) + sub);
        }
        #pragma unroll
        for (int k = 0; k < 4; k++) {
            int de = hi ? d[2*k+1] : d[2*k];
            b[k] = __ldg(reinterpret_cast<const uint4*>(
                       g_xh + (long long)de * HIDDEN + HALF) + sub);
        }

        // Per-lane partial dots (8 elements each).
        float v[4];
        #pragma unroll
        for (int k = 0; k < 4; k++)
            v[k] = dot8h(a[k], b[k]);

        // 16-lane merging butterfly. v[k] holds edge (2k + hi)'s partial.
        // Level 1 (xor 1): 4 -> 2 arrays, select by lane bit 0.
        float e0 = v[0] + __shfl_xor_sync(0xffffffffu, v[0], 1);
        float e1 = v[1] + __shfl_xor_sync(0xffffffffu, v[1], 1);
        float m0 = (lane & 1) ? e1 : e0;
        float e2 = v[2] + __shfl_xor_sync(0xffffffffu, v[2], 1);
        float e3 = v[3] + __shfl_xor_sync(0xffffffffu, v[3], 1);
        float m1 = (lane & 1) ? e3 : e2;
        // Level 2 (xor 2): 2 -> 1 array, select by lane bit 1.
        float f0 = m0 + __shfl_xor_sync(0xffffffffu, m0, 2);
        float f1 = m1 + __shfl_xor_sync(0xffffffffu, m1, 2);
        float m  = (lane & 2) ? f1 : f0;
        // Finish the 16-lane tree.
        m += __shfl_xor_sync(0xffffffffu, m, 4);
        m += __shfl_xor_sync(0xffffffffu, m, 8);
        // lane l now holds the full dot of edge 2*(l&3) + (l>>4).

        if ((lane & 12) == 0)
            out[base + 2 * (lane & 3) + hi] = sigmoidf(m);
    } else {
        // Tail: up to EPW-1 edges, scalar warp-per-edge path (uint2/lane).
        for (int e = base; e < n_edges; e++) {
            int s = __ldg(&eidx[e]);
            int d = __ldg(&eidx[n_edges + e]);
            uint2 ua = __ldg(reinterpret_cast<const uint2*>(
                           g_xh + (long long)s * HIDDEN) + lane);
            uint2 ub = __ldg(reinterpret_cast<const uint2*>(
                           g_xh + (long long)d * HIDDEN + HALF) + lane);
            const __half2* ah = reinterpret_cast<const __half2*>(&ua);
            const __half2* bh = reinterpret_cast<const __half2*>(&ub);
            float dot = 0.0f;
            #pragma unroll
            for (int i = 0; i < 2; i++) {
                float2 fa = __half22float2(ah[i]);
                float2 fb = __half22float2(bh[i]);
                dot = fmaf(fa.x, fb.x, dot);
                dot = fmaf(fa.y, fb.y, dot);
            }
            #pragma unroll
            for (int off = 16; off > 0; off >>= 1)
                dot += __shfl_xor_sync(0xffffffffu, dot, off);
            if (lane == 0)
                out[e] = sigmoidf(dot);
        }
    }
}

extern "C" void kernel_launch(void* const* d_in, const int* in_sizes, int n_in,
                              void* d_out, int out_size)
{
    const float* x    = (const float*)d_in[0];
    const int*   eidx = (const int*)d_in[1];
    float*       out  = (float*)d_out;

    int n_x     = in_sizes[0];       // 25.6M floats (divisible by 8)
    int n_edges = in_sizes[1] / 2;   // edge_label_index has 2*N_EDGES elements

    // Kernel 1: convert table to fp16 (8 floats per thread).
    int n8 = n_x / 8;
    convert_kernel<<<(n8 + 255) / 256, 256>>>(x, n8);

    // Kernel 2: gather + dot + sigmoid.
    const int threads = 256;                       // 8 warps/block
    int warps_per_block = threads / 32;
    int edges_per_block = warps_per_block * EPW;
    int blocks = (n_edges + edges_per_block - 1) / edges_per_block;
    edge_dot_sigmoid_kernel<<<blocks, threads>>>(eidx, out, n_edges);
}

// round 13
// speedup vs baseline: 1.4765x; 1.1353x over previous
#include <cuda_runtime.h>
#include <cuda_fp16.h>

// out[e] = sigmoid( dot( x[src[e], 0:128], x[dst[e], 128:256] ) )
// x: [100000, 256] fp32. edge_label_index: [2, N_EDGES] int32 on device.
//
// Two kernels per launch:
//  1) convert x (102 MB fp32) -> static __device__ fp16 table (51.2 MB).
//     fp32 reads are evict_first, fp16 writes evict_last: the table stays
//     in L2 for the gather kernel (producer->consumer handoff).
//  2) gather: 8 edges/warp, per-lane uint2 (4 halves) per half-row
//     (R11 shape — fastest measured), dot via packed fma.rn.f32x2,
//     merging-butterfly reduction (16 SHFLs for 8 edges).

#define N_NODES 100000
#define HIDDEN  256
#define HALF    128
#define EPW     8     // edges per warp

__device__ static __half g_xh[(size_t)N_NODES * HIDDEN];   // 51.2 MB scratch

__device__ __forceinline__ float sigmoidf(float v)
{
    return __fdividef(1.0f, 1.0f + __expf(-v));
}

__device__ __forceinline__ unsigned long long pol_evict_first()
{
    unsigned long long p;
    asm("createpolicy.fractional.L2::evict_first.b64 %0, 1.0;" : "=l"(p));
    return p;
}
__device__ __forceinline__ unsigned long long pol_evict_last()
{
    unsigned long long p;
    asm("createpolicy.fractional.L2::evict_last.b64 %0, 1.0;" : "=l"(p));
    return p;
}

// ---------------- kernel 1: fp32 -> fp16 table ----------------
__global__ __launch_bounds__(256)
void convert_kernel(const float* __restrict__ x, int n8)
{
    int i = blockIdx.x * blockDim.x + threadIdx.x;
    if (i >= n8) return;

    unsigned long long pf = pol_evict_first();
    unsigned long long pl = pol_evict_last();

    const float4* src = reinterpret_cast<const float4*>(x) + 2 * i;
    float4 v0, v1;
    asm("ld.global.nc.L2::cache_hint.v4.f32 {%0,%1,%2,%3}, [%4], %5;"
        : "=f"(v0.x), "=f"(v0.y), "=f"(v0.z), "=f"(v0.w) : "l"(src), "l"(pf));
    asm("ld.global.nc.L2::cache_hint.v4.f32 {%0,%1,%2,%3}, [%4], %5;"
        : "=f"(v1.x), "=f"(v1.y), "=f"(v1.z), "=f"(v1.w) : "l"(src + 1), "l"(pf));

    __half2 h0 = __floats2half2_rn(v0.x, v0.y);
    __half2 h1 = __floats2half2_rn(v0.z, v0.w);
    __half2 h2 = __floats2half2_rn(v1.x, v1.y);
    __half2 h3 = __floats2half2_rn(v1.z, v1.w);
    unsigned u0 = *reinterpret_cast<unsigned*>(&h0);
    unsigned u1 = *reinterpret_cast<unsigned*>(&h1);
    unsigned u2 = *reinterpret_cast<unsigned*>(&h2);
    unsigned u3 = *reinterpret_cast<unsigned*>(&h3);

    uint4* dst = reinterpret_cast<uint4*>(g_xh) + i;
    asm volatile("st.global.L2::cache_hint.v4.b32 [%0], {%1,%2,%3,%4}, %5;"
                 :: "l"(dst), "r"(u0), "r"(u1), "r"(u2), "r"(u3), "l"(pl)
                 : "memory");
}

// dot of 4 halves vs 4 halves using packed f32x2 FMA, fp32 accumulation
__device__ __forceinline__ float dot4h(uint2 ua, uint2 ub)
{
    __half2 a0 = *reinterpret_cast<__half2*>(&ua.x);
    __half2 a1 = *reinterpret_cast<__half2*>(&ua.y);
    __half2 b0 = *reinterpret_cast<__half2*>(&ub.x);
    __half2 b1 = *reinterpret_cast<__half2*>(&ub.y);
    float2 fa0 = __half22float2(a0), fa1 = __half22float2(a1);
    float2 fb0 = __half22float2(b0), fb1 = __half22float2(b1);

    unsigned long long A0, B0, A1, B1, ACC;
    asm("mov.b64 %0, {%1, %2};" : "=l"(A0) : "f"(fa0.x), "f"(fa0.y));
    asm("mov.b64 %0, {%1, %2};" : "=l"(B0) : "f"(fb0.x), "f"(fb0.y));
    asm("mov.b64 %0, {%1, %2};" : "=l"(A1) : "f"(fa1.x), "f"(fa1.y));
    asm("mov.b64 %0, {%1, %2};" : "=l"(B1) : "f"(fb1.x), "f"(fb1.y));
    asm("mul.rn.f32x2 %0, %1, %2;" : "=l"(ACC) : "l"(A0), "l"(B0));
    asm("fma.rn.f32x2 %0, %1, %2, %3;" : "=l"(ACC) : "l"(A1), "l"(B1), "l"(ACC));
    float lo, hi;
    asm("mov.b64 {%0, %1}, %2;" : "=f"(lo), "=f"(hi) : "l"(ACC));
    return lo + hi;
}

// ---------------- kernel 2: edge gather + dot + sigmoid ----------------
__global__ __launch_bounds__(256)
void edge_dot_sigmoid_kernel(const int* __restrict__ eidx,
                             float* __restrict__ out,
                             int n_edges)
{
    int warp = (blockIdx.x * blockDim.x + threadIdx.x) >> 5;
    int lane = threadIdx.x & 31;
    int base = warp * EPW;
    if (base >= n_edges) return;

    if (base + EPW <= n_edges) {
        // Warp-uniform vector index loads (16B requests).
        int4 s0 = __ldg(reinterpret_cast<const int4*>(eidx + base));
        int4 s1 = __ldg(reinterpret_cast<const int4*>(eidx + base + 4));
        int4 d0 = __ldg(reinterpret_cast<const int4*>(eidx + n_edges + base));
        int4 d1 = __ldg(reinterpret_cast<const int4*>(eidx + n_edges + base + 4));
        int s[EPW] = {s0.x, s0.y, s0.z, s0.w, s1.x, s1.y, s1.z, s1.w};
        int d[EPW] = {d0.x, d0.y, d0.z, d0.w, d1.x, d1.y, d1.z, d1.w};

        // Issue all 16 LDG.64 gathers before any math.
        uint2 a[EPW], b[EPW];
        #pragma unroll
        for (int k = 0; k < EPW; k++)
            a[k] = __ldg(reinterpret_cast<const uint2*>(
                       g_xh + (long long)s[k] * HIDDEN) + lane);
        #pragma unroll
        for (int k = 0; k < EPW; k++)
            b[k] = __ldg(reinterpret_cast<const uint2*>(
                       g_xh + (long long)d[k] * HIDDEN + HALF) + lane);

        float v[EPW];
        #pragma unroll
        for (int k = 0; k < EPW; k++)
            v[k] = dot4h(a[k], b[k]);

        // Merging butterfly: 8 -> 4 -> 2 -> 1 arrays, then finish the tree.
        float m0[4];
        #pragma unroll
        for (int k = 0; k < 4; k++) {
            float e0 = v[2*k]   + __shfl_xor_sync(0xffffffffu, v[2*k],   1);
            float e1 = v[2*k+1] + __shfl_xor_sync(0xffffffffu, v[2*k+1], 1);
            m0[k] = (lane & 1) ? e1 : e0;
        }
        float m1[2];
        #pragma unroll
        for (int k = 0; k < 2; k++) {
            float e0 = m0[2*k]   + __shfl_xor_sync(0xffffffffu, m0[2*k],   2);
            float e1 = m0[2*k+1] + __shfl_xor_sync(0xffffffffu, m0[2*k+1], 2);
            m1[k] = (lane & 2) ? e1 : e0;
        }
        float e0 = m1[0] + __shfl_xor_sync(0xffffffffu, m1[0], 4);
        float e1 = m1[1] + __shfl_xor_sync(0xffffffffu, m1[1], 4);
        float m2 = (lane & 4) ? e1 : e0;
        m2 += __shfl_xor_sync(0xffffffffu, m2, 8);
        m2 += __shfl_xor_sync(0xffffffffu, m2, 16);
        // lane l now holds the full dot for edge (l & 7).

        if (lane < EPW)
            out[base + lane] = sigmoidf(m2);
    } else {
        // Tail: up to EPW-1 edges, scalar path.
        for (int e = base; e < n_edges; e++) {
            int s = __ldg(&eidx[e]);
            int d = __ldg(&eidx[n_edges + e]);
            uint2 ua = __ldg(reinterpret_cast<const uint2*>(
                           g_xh + (long long)s * HIDDEN) + lane);
            uint2 ub = __ldg(reinterpret_cast<const uint2*>(
                           g_xh + (long long)d * HIDDEN + HALF) + lane);
            float dot = dot4h(ua, ub);
            #pragma unroll
            for (int off = 16; off > 0; off >>= 1)
                dot += __shfl_xor_sync(0xffffffffu, dot, off);
            if (lane == 0)
                out[e] = sigmoidf(dot);
        }
    }
}

extern "C" void kernel_launch(void* const* d_in, const int* in_sizes, int n_in,
                              void* d_out, int out_size)
{
    const float* x    = (const float*)d_in[0];
    const int*   eidx = (const int*)d_in[1];
    float*       out  = (float*)d_out;

    int n_x     = in_sizes[0];       // 25.6M floats (divisible by 8)
    int n_edges = in_sizes[1] / 2;   // edge_label_index has 2*N_EDGES elements

    // Kernel 1: convert table to fp16 (8 floats per thread).
    int n8 = n_x / 8;
    convert_kernel<<<(n8 + 255) / 256, 256>>>(x, n8);

    // Kernel 2: gather + dot + sigmoid.
    const int threads = 256;                       // 8 warps/block
    int warps_per_block = threads / 32;
    int edges_per_block = warps_per_block * EPW;
    int blocks = (n_edges + edges_per_block - 1) / edges_per_block;
    edge_dot_sigmoid_kernel<<<blocks, threads>>>(eidx, out, n_edges);
}